// round 15
// baseline (speedup 1.0000x reference)
#include <cuda_runtime.h>
#include <cuda_bf16.h>
#include <mma.h>
#include <cstdint>
#include <cstddef>

using namespace nvcuda;

#define N_NODES 50000
#define N_EDGES 800000
#define NFEAT 128
#define NHID 256
#define NCLASS 64
#define NPART 196           // ceil(50000/256)

// ===========================================================================
// device scratch  (never passed as kernel args — GB300 ATS reads host shadow)
// ===========================================================================
__device__ int   g_is64;
__device__ int   g_deg [N_NODES];
__device__ int   g_part[256];
__device__ int   g_off [N_NODES + 1];
__device__ int   g_cur [N_NODES];
__device__ int   g_csr [N_EDGES];
__device__ float g_meanx[(size_t)N_NODES * NFEAT];
__device__ float g_h    [(size_t)N_NODES * NHID];
__device__ float g_p2   [(size_t)N_NODES * NCLASS];
// pre-split, pre-transposed weights, B^T layout [n][k], k-stride 256
__device__ __nv_bfloat16 g_bt1_hi[256 * 256];
__device__ __nv_bfloat16 g_bt1_lo[256 * 256];
__device__ __nv_bfloat16 g_bt2_hi[128 * 256];
__device__ __nv_bfloat16 g_bt2_lo[128 * 256];

__device__ __forceinline__ uint2 pack4_hi_lo(const float* v, uint2& lo_out) {
    uint2 hi;
    uint32_t h[4], l[4];
    #pragma unroll
    for (int q = 0; q < 4; ++q) {
        __nv_bfloat16 hb = __float2bfloat16_rn(v[q]);
        __nv_bfloat16 lb = __float2bfloat16_rn(v[q] - __bfloat162float(hb));
        h[q] = (uint32_t)__bfloat16_as_ushort(hb);
        l[q] = (uint32_t)__bfloat16_as_ushort(lb);
    }
    hi.x = h[0] | (h[1] << 16);
    hi.y = h[2] | (h[3] << 16);
    lo_out.x = l[0] | (l[1] << 16);
    lo_out.y = l[2] | (l[3] << 16);
    return hi;
}

// ===========================================================================
// small kernels
// ===========================================================================
__device__ __forceinline__ int load_idx(const void* __restrict__ ei, long long pos, int is64) {
    if (is64) return (int)((const long long*)ei)[pos];
    return ((const int*)ei)[pos];
}

// zero degrees + (block 0) edge-index dtype detection
__global__ void zero_deg_kernel(const int* __restrict__ ei32) {
    int i = blockIdx.x * blockDim.x + threadIdx.x;
    if (i < N_NODES) g_deg[i] = 0;
    if (blockIdx.x == 0 && threadIdx.x == 0) {
        int allz = 1;
        #pragma unroll
        for (int q = 0; q < 32; ++q)
            if (ei32[2 * q + 1] != 0) { allz = 0; break; }
        g_is64 = allz;
    }
}

__global__ void hist_kernel(const void* __restrict__ ei) {
    int e = blockIdx.x * blockDim.x + threadIdx.x;
    if (e < N_EDGES) {
        int d = load_idx(ei, (long long)N_EDGES + e, g_is64);
        atomicAdd(&g_deg[d], 1);
    }
}

__device__ __forceinline__ int warp_incl_scan(int v, int lane) {
    #pragma unroll
    for (int d = 1; d < 32; d <<= 1) {
        int t = __shfl_up_sync(0xffffffffu, v, d);
        if (lane >= d) v += t;
    }
    return v;
}

__global__ void scan_part_kernel() {
    int b = blockIdx.x, t = threadIdx.x;
    int idx = b * 256 + t;
    int v = (idx < N_NODES) ? g_deg[idx] : 0;
    int s = v;
    #pragma unroll
    for (int d = 16; d; d >>= 1) s += __shfl_xor_sync(0xffffffffu, s, d);
    __shared__ int ws[8];
    if ((t & 31) == 0) ws[t >> 5] = s;
    __syncthreads();
    if (t == 0) {
        int tot = 0;
        #pragma unroll
        for (int i = 0; i < 8; ++i) tot += ws[i];
        g_part[b] = tot;
    }
}

__global__ void scan_top_kernel() {
    int t = threadIdx.x;
    int lane = t & 31, w = t >> 5;
    int v = (t < NPART) ? g_part[t] : 0;
    int inc = warp_incl_scan(v, lane);
    __shared__ int ws[8];
    if (lane == 31) ws[w] = inc;
    __syncthreads();
    if (t == 0) {
        int run = 0;
        #pragma unroll
        for (int i = 0; i < 8; ++i) { int x = ws[i]; ws[i] = run; run += x; }
    }
    __syncthreads();
    int excl = inc - v + ws[w];
    if (t < NPART) g_part[t] = excl;
    if (t == 0) g_off[N_NODES] = N_EDGES;
}

__global__ void scan_fin_kernel() {
    int b = blockIdx.x, t = threadIdx.x;
    int idx = b * 256 + t;
    int lane = t & 31, w = t >> 5;
    int v = (idx < N_NODES) ? g_deg[idx] : 0;
    int inc = warp_incl_scan(v, lane);
    __shared__ int ws[8];
    if (lane == 31) ws[w] = inc;
    __syncthreads();
    if (t == 0) {
        int run = 0;
        #pragma unroll
        for (int i = 0; i < 8; ++i) { int x = ws[i]; ws[i] = run; run += x; }
    }
    __syncthreads();
    int excl = inc - v + ws[w] + g_part[b];
    if (idx < N_NODES) { g_off[idx] = excl; g_cur[idx] = excl; }
}

__global__ void fill_kernel(const void* __restrict__ ei) {
    int e = blockIdx.x * blockDim.x + threadIdx.x;
    if (e < N_EDGES) {
        int is64 = g_is64;
        int s = load_idx(ei, e, is64);
        int d = load_idx(ei, (long long)N_EDGES + e, is64);
        int pos = atomicAdd(&g_cur[d], 1);
        g_csr[pos] = s;
    }
}

// warp per node: meanx[n] = mean over in-edges of x[src]
__global__ void agg_x_kernel(const float* __restrict__ x) {
    int gi = blockIdx.x * blockDim.x + threadIdx.x;
    int n = gi >> 5, lane = gi & 31;
    if (n >= N_NODES) return;
    int beg = g_off[n], end = g_off[n + 1];
    float4 acc = make_float4(0.f, 0.f, 0.f, 0.f);
    for (int i = beg; i < end; ++i) {
        int s = g_csr[i];
        const float4 v = *(const float4*)(x + (size_t)s * NFEAT + lane * 4);
        acc.x += v.x; acc.y += v.y; acc.z += v.z; acc.w += v.w;
    }
    float inv = 1.0f / fmaxf((float)(end - beg), 1.0f);
    acc.x *= inv; acc.y *= inv; acc.z *= inv; acc.w *= inv;
    *(float4*)(g_meanx + (size_t)n * NFEAT + lane * 4) = acc;
}

// warp per node: out[n] += mean over in-edges of p2[src]
__global__ void agg_p_kernel(float* __restrict__ out) {
    int gi = blockIdx.x * blockDim.x + threadIdx.x;
    int n = gi >> 5, lane = gi & 31;
    if (n >= N_NODES) return;
    int beg = g_off[n], end = g_off[n + 1];
    float2 acc = make_float2(0.f, 0.f);
    for (int i = beg; i < end; ++i) {
        int s = g_csr[i];
        const float2 v = *(const float2*)(g_p2 + (size_t)s * NCLASS + lane * 2);
        acc.x += v.x; acc.y += v.y;
    }
    float inv = 1.0f / fmaxf((float)(end - beg), 1.0f);
    float* o = out + (size_t)n * NCLASS + lane * 2;
    o[0] += acc.x * inv;
    o[1] += acc.y * inv;
}

// ===========================================================================
// weight prepack: transpose + bf16 hi/lo split
// ===========================================================================
__global__ void prepack_kernel(const float* __restrict__ W1n,
                               const float* __restrict__ W1r,
                               const float* __restrict__ W2n,
                               const float* __restrict__ W2r) {
    int i = blockIdx.x * blockDim.x + threadIdx.x;
    const int SZ1 = 256 * 256;
    const int SZ2 = 128 * 256;
    if (i < SZ1) {
        int n = i >> 8, k = i & 255;
        float a = (k < 128) ? W1n[(size_t)k * NHID + n] : W1r[(size_t)(k - 128) * NHID + n];
        __nv_bfloat16 h = __float2bfloat16_rn(a);
        __nv_bfloat16 l = __float2bfloat16_rn(a - __bfloat162float(h));
        g_bt1_hi[i] = h; g_bt1_lo[i] = l;
    } else if (i < SZ1 + SZ2) {
        int j = i - SZ1;
        int n = j >> 8, k = j & 255;
        float a = (n < 64) ? W2n[(size_t)k * NCLASS + n] : W2r[(size_t)k * NCLASS + (n - 64)];
        __nv_bfloat16 h = __float2bfloat16_rn(a);
        __nv_bfloat16 l = __float2bfloat16_rn(a - __bfloat162float(h));
        g_bt2_hi[j] = h; g_bt2_lo[j] = l;
    }
}

// ===========================================================================
// split-bf16 GEMM via nvcuda::wmma — R14 tile + launch_bounds(256,3) winner,
// now with 2-stage smem double buffering (1 sync/chunk; loads of chunk c+1
// overlap mma of chunk c across warps). Dynamic smem: 2 x 30720 B.
// CTA tile 128m x 64n; 8 warps 4(m) x 2(n); warp 32x32 = 2x2 frags.
// K = 256 in 8 chunks of 32. D = Ah*Bh + Ah*Bl + Al*Bh.
// mode 1: A = [meanx | x]  (lda 128 each), out = g_h = relu(D + b1)
// mode 2: A = g_h (lda 256), colBase 0 -> p2 ; colBase 64 -> out + b2
// ===========================================================================
#define A_LD 40   // 32 k + 8 pad
#define B_LD 40
#define STAGE_BYTES 30720   // ah(10240) + al(10240) + bh(5120) + bl(5120)
#define SMEM_DYN (2 * STAGE_BYTES)   // 61440; >= stage area (32768)

__global__ __launch_bounds__(256, 3)
void wmma_gemm_kernel(const float* __restrict__ x,
                      const float* __restrict__ bias,
                      float* __restrict__ out2,
                      int mode) {
    extern __shared__ __align__(16) char dyn_sm[];

    const int rowBase = blockIdx.x * 128;
    const int colBase = blockIdx.y * 64;
    const int tid = threadIdx.x;
    const int wid = tid >> 5;
    const int warpM = wid & 3;   // 0..3 -> 32 rows each
    const int warpN = wid >> 2;  // 0..1 -> 32 cols each

    // stage pointers
    __nv_bfloat16* AH[2]; __nv_bfloat16* AL[2];
    __nv_bfloat16* BH[2]; __nv_bfloat16* BL[2];
    #pragma unroll
    for (int s = 0; s < 2; ++s) {
        char* base = dyn_sm + s * STAGE_BYTES;
        AH[s] = (__nv_bfloat16*)(base);
        AL[s] = (__nv_bfloat16*)(base + 10240);
        BH[s] = (__nv_bfloat16*)(base + 20480);
        BL[s] = (__nv_bfloat16*)(base + 25600);
    }
    float* stage = (float*)dyn_sm;   // epilogue aliases buffers (after loop)

    // resolve scratch INSIDE device code
    const float* A0 = (mode == 1) ? g_meanx : g_h;
    const float* A1 = (mode == 1) ? x       : g_h + 128;
    const int    lda = (mode == 1) ? NFEAT  : NHID;
    const __nv_bfloat16* BT_hi = (mode == 1) ? g_bt1_hi : g_bt2_hi;
    const __nv_bfloat16* BT_lo = (mode == 1) ? g_bt1_lo : g_bt2_lo;

    wmma::fragment<wmma::accumulator, 16, 16, 16, float> acc[2][2];
    #pragma unroll
    for (int i = 0; i < 2; ++i)
        #pragma unroll
        for (int j = 0; j < 2; ++j) wmma::fill_fragment(acc[i][j], 0.0f);

    // ---- chunk loader: global -> (split) -> smem stage buf ----
    #define LOAD_CHUNK(c, buf) do {                                             \
        const float* Asrc = ((c) < 4) ? A0 : A1;                                \
        const int akk = ((c) & 3) * 32;                                         \
        const int kk = (c) * 32;                                                \
        _Pragma("unroll")                                                       \
        for (int G = tid; G < 1024; G += 256) {                                 \
            int row = G >> 3, g = G & 7;                                        \
            int gr = rowBase + row;                                             \
            float4 u = make_float4(0.f, 0.f, 0.f, 0.f);                         \
            if (gr < N_NODES)                                                   \
                u = *(const float4*)(Asrc + (size_t)gr * lda + akk + g * 4);    \
            float v[4] = {u.x, u.y, u.z, u.w};                                  \
            int base = row * A_LD + g * 4;                                      \
            uint2 lo, hi = pack4_hi_lo(v, lo);                                  \
            *(uint2*)&AH[buf][base] = hi;                                       \
            *(uint2*)&AL[buf][base] = lo;                                       \
        }                                                                       \
        {                                                                       \
            int n = tid >> 2, g = tid & 3;                                      \
            size_t boff = (size_t)(colBase + n) * 256 + kk + g * 8;             \
            uint4 vh = *(const uint4*)(BT_hi + boff);                           \
            uint4 vl = *(const uint4*)(BT_lo + boff);                           \
            *(uint4*)&BH[buf][n * B_LD + g * 8] = vh;                           \
            *(uint4*)&BL[buf][n * B_LD + g * 8] = vl;                           \
        }                                                                       \
    } while (0)

    LOAD_CHUNK(0, 0);
    __syncthreads();

    for (int c = 0; c < 8; ++c) {
        const int cur = c & 1;
        // loads for next chunk go to the other buffer; overlap with mma below
        if (c + 1 < 8) LOAD_CHUNK(c + 1, cur ^ 1);

        // ---- compute chunk c: 2 k16 steps ----
        #pragma unroll
        for (int ks = 0; ks < 2; ++ks) {
            wmma::fragment<wmma::matrix_a, 16, 16, 16, __nv_bfloat16, wmma::row_major> aH[2], aL[2];
            wmma::fragment<wmma::matrix_b, 16, 16, 16, __nv_bfloat16, wmma::col_major> bH[2], bL[2];
            #pragma unroll
            for (int mt = 0; mt < 2; ++mt) {
                int r0 = warpM * 32 + mt * 16;
                wmma::load_matrix_sync(aH[mt], &AH[cur][r0 * A_LD + ks * 16], A_LD);
                wmma::load_matrix_sync(aL[mt], &AL[cur][r0 * A_LD + ks * 16], A_LD);
            }
            #pragma unroll
            for (int nt = 0; nt < 2; ++nt) {
                int n0 = warpN * 32 + nt * 16;
                wmma::load_matrix_sync(bH[nt], &BH[cur][n0 * B_LD + ks * 16], B_LD);
                wmma::load_matrix_sync(bL[nt], &BL[cur][n0 * B_LD + ks * 16], B_LD);
            }
            #pragma unroll
            for (int mt = 0; mt < 2; ++mt)
                #pragma unroll
                for (int nt = 0; nt < 2; ++nt) {
                    wmma::mma_sync(acc[mt][nt], aH[mt], bH[nt], acc[mt][nt]);
                    wmma::mma_sync(acc[mt][nt], aH[mt], bL[nt], acc[mt][nt]);
                    wmma::mma_sync(acc[mt][nt], aL[mt], bH[nt], acc[mt][nt]);
                }
        }
        // one barrier per chunk: publishes next buffer, protects current from
        // being overwritten two iterations later
        __syncthreads();
    }
    #undef LOAD_CHUNK

    // ---- epilogue: stage in smem, then bias/relu on copy-out ----
    #pragma unroll
    for (int mt = 0; mt < 2; ++mt)
        #pragma unroll
        for (int nt = 0; nt < 2; ++nt) {
            int r0 = warpM * 32 + mt * 16;
            int c0 = warpN * 32 + nt * 16;
            wmma::store_matrix_sync(&stage[r0 * 64 + c0], acc[mt][nt], 64,
                                    wmma::mem_row_major);
        }
    __syncthreads();

    #pragma unroll
    for (int G = tid; G < 2048; G += 256) {
        int row = G >> 4, g = G & 15;
        int gr = rowBase + row;
        if (gr >= N_NODES) continue;
        float4 v = *(const float4*)&stage[row * 64 + g * 4];
        float w[4] = {v.x, v.y, v.z, v.w};
        if (mode == 1) {
            int col = colBase + g * 4;
            #pragma unroll
            for (int q = 0; q < 4; ++q) w[q] = fmaxf(w[q] + bias[col + q], 0.f);
            *(float4*)(g_h + (size_t)gr * NHID + col) = make_float4(w[0], w[1], w[2], w[3]);
        } else {
            int col = g * 4;  // local 0..63
            if (colBase == 0) {
                *(float4*)(g_p2 + (size_t)gr * NCLASS + col) = make_float4(w[0], w[1], w[2], w[3]);
            } else {
                #pragma unroll
                for (int q = 0; q < 4; ++q) w[q] += bias[col + q];
                *(float4*)(out2 + (size_t)gr * NCLASS + col) = make_float4(w[0], w[1], w[2], w[3]);
            }
        }
    }
}

// ===========================================================================
extern "C" void kernel_launch(void* const* d_in, const int* in_sizes, int n_in,
                              void* d_out, int out_size) {
    const float* x   = (const float*)d_in[0];
    const void*  ei  = d_in[1];
    const float* W1n = (const float*)d_in[2];
    const float* W1r = (const float*)d_in[3];
    const float* b1  = (const float*)d_in[4];
    const float* W2n = (const float*)d_in[5];
    const float* W2r = (const float*)d_in[6];
    const float* b2  = (const float*)d_in[7];
    float* out = (float*)d_out;

    // one-time: allow >48KB dynamic smem on the GEMM (host attr, no alloc)
    static bool attr_done = false;
    if (!attr_done) {
        cudaFuncSetAttribute(wmma_gemm_kernel,
                             cudaFuncAttributeMaxDynamicSharedMemorySize, SMEM_DYN);
        attr_done = true;
    }

    // zero degrees + dtype detect (fused) ; weight prepack
    zero_deg_kernel<<<(N_NODES + 255) / 256, 256>>>((const int*)ei);
    prepack_kernel<<<(256 * 256 + 128 * 256 + 255) / 256, 256>>>(W1n, W1r, W2n, W2r);

    // CSR build
    hist_kernel<<<(N_EDGES + 255) / 256, 256>>>(ei);
    scan_part_kernel<<<NPART, 256>>>();
    scan_top_kernel<<<1, 256>>>();
    scan_fin_kernel<<<NPART, 256>>>();
    fill_kernel<<<(N_EDGES + 255) / 256, 256>>>(ei);

    // layer1 aggregation
    {
        long long threads = (long long)N_NODES * 32;
        agg_x_kernel<<<(int)((threads + 255) / 256), 256>>>(x);
    }
    // layer1 GEMM (wmma): h = relu([meanx|x] @ [W1n;W1r] + b1)
    {
        dim3 grid((N_NODES + 127) / 128, NHID / 64);
        wmma_gemm_kernel<<<grid, 256, SMEM_DYN>>>(x, b1, nullptr, 1);
    }
    // layer2 fused GEMM: colBase 0 -> p2 = h@W2n ; colBase 64 -> out = h@W2r + b2
    {
        dim3 grid((N_NODES + 127) / 128, 2);
        wmma_gemm_kernel<<<grid, 256, SMEM_DYN>>>(x, b2, out, 2);
    }
    // layer2 aggregation
    {
        long long threads = (long long)N_NODES * 32;
        agg_p_kernel<<<(int)((threads + 255) / 256), 256>>>(out);
    }
}

// round 16
// speedup vs baseline: 1.2033x; 1.2033x over previous
#include <cuda_runtime.h>
#include <cuda_bf16.h>
#include <mma.h>
#include <cstdint>
#include <cstddef>

using namespace nvcuda;

#define N_NODES 50000
#define N_EDGES 800000
#define NFEAT 128
#define NHID 256
#define NCLASS 64
#define NPART 196           // ceil(50000/256)

// ===========================================================================
// device scratch  (never passed as kernel args — GB300 ATS reads host shadow)
// ===========================================================================
__device__ int   g_is64;
__device__ int   g_deg [N_NODES];
__device__ int   g_part[256];
__device__ int   g_off [N_NODES + 1];
__device__ int   g_cur [N_NODES];
__device__ int   g_csr [N_EDGES];
__device__ float g_meanx[(size_t)N_NODES * NFEAT];
__device__ float g_h    [(size_t)N_NODES * NHID];
__device__ float g_p2   [(size_t)N_NODES * NCLASS];
// pre-split, pre-transposed weights, B^T layout [n][k], k-stride 256
__device__ __nv_bfloat16 g_bt1_hi[256 * 256];
__device__ __nv_bfloat16 g_bt1_lo[256 * 256];
__device__ __nv_bfloat16 g_bt2_hi[128 * 256];
__device__ __nv_bfloat16 g_bt2_lo[128 * 256];

// fp32x4 -> packed bf16 hi/lo via paired cvt.rn.bf16x2.f32 (same rounding as
// scalar __float2bfloat16_rn, half the CVT instruction count, no pack ORs)
__device__ __forceinline__ uint2 pack4_hi_lo(const float* v, uint2& lo_out) {
    __nv_bfloat162 h01 = __floats2bfloat162_rn(v[0], v[1]);
    __nv_bfloat162 h23 = __floats2bfloat162_rn(v[2], v[3]);
    float2 f01 = __bfloat1622float2(h01);
    float2 f23 = __bfloat1622float2(h23);
    __nv_bfloat162 l01 = __floats2bfloat162_rn(v[0] - f01.x, v[1] - f01.y);
    __nv_bfloat162 l23 = __floats2bfloat162_rn(v[2] - f23.x, v[3] - f23.y);
    uint2 hi;
    hi.x = *(const uint32_t*)&h01;
    hi.y = *(const uint32_t*)&h23;
    lo_out.x = *(const uint32_t*)&l01;
    lo_out.y = *(const uint32_t*)&l23;
    return hi;
}

// ===========================================================================
// small kernels
// ===========================================================================
__device__ __forceinline__ int load_idx(const void* __restrict__ ei, long long pos, int is64) {
    if (is64) return (int)((const long long*)ei)[pos];
    return ((const int*)ei)[pos];
}

// zero degrees + (block 0) edge-index dtype detection
__global__ void zero_deg_kernel(const int* __restrict__ ei32) {
    int i = blockIdx.x * blockDim.x + threadIdx.x;
    if (i < N_NODES) g_deg[i] = 0;
    if (blockIdx.x == 0 && threadIdx.x == 0) {
        int allz = 1;
        #pragma unroll
        for (int q = 0; q < 32; ++q)
            if (ei32[2 * q + 1] != 0) { allz = 0; break; }
        g_is64 = allz;
    }
}

__global__ void hist_kernel(const void* __restrict__ ei) {
    int e = blockIdx.x * blockDim.x + threadIdx.x;
    if (e < N_EDGES) {
        int d = load_idx(ei, (long long)N_EDGES + e, g_is64);
        atomicAdd(&g_deg[d], 1);
    }
}

__device__ __forceinline__ int warp_incl_scan(int v, int lane) {
    #pragma unroll
    for (int d = 1; d < 32; d <<= 1) {
        int t = __shfl_up_sync(0xffffffffu, v, d);
        if (lane >= d) v += t;
    }
    return v;
}

__global__ void scan_part_kernel() {
    int b = blockIdx.x, t = threadIdx.x;
    int idx = b * 256 + t;
    int v = (idx < N_NODES) ? g_deg[idx] : 0;
    int s = v;
    #pragma unroll
    for (int d = 16; d; d >>= 1) s += __shfl_xor_sync(0xffffffffu, s, d);
    __shared__ int ws[8];
    if ((t & 31) == 0) ws[t >> 5] = s;
    __syncthreads();
    if (t == 0) {
        int tot = 0;
        #pragma unroll
        for (int i = 0; i < 8; ++i) tot += ws[i];
        g_part[b] = tot;
    }
}

__global__ void scan_top_kernel() {
    int t = threadIdx.x;
    int lane = t & 31, w = t >> 5;
    int v = (t < NPART) ? g_part[t] : 0;
    int inc = warp_incl_scan(v, lane);
    __shared__ int ws[8];
    if (lane == 31) ws[w] = inc;
    __syncthreads();
    if (t == 0) {
        int run = 0;
        #pragma unroll
        for (int i = 0; i < 8; ++i) { int x = ws[i]; ws[i] = run; run += x; }
    }
    __syncthreads();
    int excl = inc - v + ws[w];
    if (t < NPART) g_part[t] = excl;
    if (t == 0) g_off[N_NODES] = N_EDGES;
}

__global__ void scan_fin_kernel() {
    int b = blockIdx.x, t = threadIdx.x;
    int idx = b * 256 + t;
    int lane = t & 31, w = t >> 5;
    int v = (idx < N_NODES) ? g_deg[idx] : 0;
    int inc = warp_incl_scan(v, lane);
    __shared__ int ws[8];
    if (lane == 31) ws[w] = inc;
    __syncthreads();
    if (t == 0) {
        int run = 0;
        #pragma unroll
        for (int i = 0; i < 8; ++i) { int x = ws[i]; ws[i] = run; run += x; }
    }
    __syncthreads();
    int excl = inc - v + ws[w] + g_part[b];
    if (idx < N_NODES) { g_off[idx] = excl; g_cur[idx] = excl; }
}

__global__ void fill_kernel(const void* __restrict__ ei) {
    int e = blockIdx.x * blockDim.x + threadIdx.x;
    if (e < N_EDGES) {
        int is64 = g_is64;
        int s = load_idx(ei, e, is64);
        int d = load_idx(ei, (long long)N_EDGES + e, is64);
        int pos = atomicAdd(&g_cur[d], 1);
        g_csr[pos] = s;
    }
}

// warp per node: meanx[n] = mean over in-edges of x[src]
__global__ void agg_x_kernel(const float* __restrict__ x) {
    int gi = blockIdx.x * blockDim.x + threadIdx.x;
    int n = gi >> 5, lane = gi & 31;
    if (n >= N_NODES) return;
    int beg = g_off[n], end = g_off[n + 1];
    float4 acc = make_float4(0.f, 0.f, 0.f, 0.f);
    for (int i = beg; i < end; ++i) {
        int s = g_csr[i];
        const float4 v = *(const float4*)(x + (size_t)s * NFEAT + lane * 4);
        acc.x += v.x; acc.y += v.y; acc.z += v.z; acc.w += v.w;
    }
    float inv = 1.0f / fmaxf((float)(end - beg), 1.0f);
    acc.x *= inv; acc.y *= inv; acc.z *= inv; acc.w *= inv;
    *(float4*)(g_meanx + (size_t)n * NFEAT + lane * 4) = acc;
}

// warp per node: out[n] += mean over in-edges of p2[src]
__global__ void agg_p_kernel(float* __restrict__ out) {
    int gi = blockIdx.x * blockDim.x + threadIdx.x;
    int n = gi >> 5, lane = gi & 31;
    if (n >= N_NODES) return;
    int beg = g_off[n], end = g_off[n + 1];
    float2 acc = make_float2(0.f, 0.f);
    for (int i = beg; i < end; ++i) {
        int s = g_csr[i];
        const float2 v = *(const float2*)(g_p2 + (size_t)s * NCLASS + lane * 2);
        acc.x += v.x; acc.y += v.y;
    }
    float inv = 1.0f / fmaxf((float)(end - beg), 1.0f);
    float* o = out + (size_t)n * NCLASS + lane * 2;
    o[0] += acc.x * inv;
    o[1] += acc.y * inv;
}

// ===========================================================================
// weight prepack: transpose + bf16 hi/lo split
// BT1 [256n][256k]: k<128 -> W1n[k][n], else W1r[k-128][n]
// BT2 [128n][256k]: n<64 -> W2n[k][n],  else W2r[k][n-64]
// ===========================================================================
__global__ void prepack_kernel(const float* __restrict__ W1n,
                               const float* __restrict__ W1r,
                               const float* __restrict__ W2n,
                               const float* __restrict__ W2r) {
    int i = blockIdx.x * blockDim.x + threadIdx.x;
    const int SZ1 = 256 * 256;
    const int SZ2 = 128 * 256;
    if (i < SZ1) {
        int n = i >> 8, k = i & 255;
        float a = (k < 128) ? W1n[(size_t)k * NHID + n] : W1r[(size_t)(k - 128) * NHID + n];
        __nv_bfloat16 h = __float2bfloat16_rn(a);
        __nv_bfloat16 l = __float2bfloat16_rn(a - __bfloat162float(h));
        g_bt1_hi[i] = h; g_bt1_lo[i] = l;
    } else if (i < SZ1 + SZ2) {
        int j = i - SZ1;
        int n = j >> 8, k = j & 255;
        float a = (n < 64) ? W2n[(size_t)k * NCLASS + n] : W2r[(size_t)k * NCLASS + (n - 64)];
        __nv_bfloat16 h = __float2bfloat16_rn(a);
        __nv_bfloat16 l = __float2bfloat16_rn(a - __bfloat162float(h));
        g_bt2_hi[j] = h; g_bt2_lo[j] = l;
    }
}

// ===========================================================================
// split-bf16 GEMM via nvcuda::wmma (m16n16k16, bf16 in, fp32 accum).
// R14 winner config: static smem single stage, __launch_bounds__(256,3).
// CTA tile 128m x 64n; 8 warps 4(m) x 2(n); warp 32x32 = 2x2 frags.
// K = 256 in 8 chunks of 32. D = Ah*Bh + Ah*Bl + Al*Bh.
// mode 1: A = [meanx | x]  (lda 128 each), out = g_h = relu(D + b1)
// mode 2: A = g_h (lda 256), colBase 0 -> p2 ; colBase 64 -> out + b2
// ===========================================================================
#define A_LD 40   // 32 k + 8 pad
#define B_LD 40

__global__ __launch_bounds__(256, 3)
void wmma_gemm_kernel(const float* __restrict__ x,
                      const float* __restrict__ bias,
                      float* __restrict__ out2,
                      int mode) {
    __shared__ __align__(16) union {
        struct {
            __nv_bfloat16 ah[128 * A_LD];
            __nv_bfloat16 al[128 * A_LD];
            __nv_bfloat16 bh[64 * B_LD];
            __nv_bfloat16 bl[64 * B_LD];
        } t;
        float stage[128 * 64];
    } sm;

    const int rowBase = blockIdx.x * 128;
    const int colBase = blockIdx.y * 64;
    const int tid = threadIdx.x;
    const int wid = tid >> 5;
    const int warpM = wid & 3;   // 0..3 -> 32 rows each
    const int warpN = wid >> 2;  // 0..1 -> 32 cols each

    // resolve scratch INSIDE device code
    const float* A0 = (mode == 1) ? g_meanx : g_h;
    const float* A1 = (mode == 1) ? x       : g_h + 128;
    const int    lda = (mode == 1) ? NFEAT  : NHID;
    const __nv_bfloat16* BT_hi = (mode == 1) ? g_bt1_hi : g_bt2_hi;
    const __nv_bfloat16* BT_lo = (mode == 1) ? g_bt1_lo : g_bt2_lo;

    wmma::fragment<wmma::accumulator, 16, 16, 16, float> acc[2][2];
    #pragma unroll
    for (int i = 0; i < 2; ++i)
        #pragma unroll
        for (int j = 0; j < 2; ++j) wmma::fill_fragment(acc[i][j], 0.0f);

    for (int c = 0; c < 8; ++c) {
        const int kk = c * 32;
        const float* Asrc = (c < 4) ? A0 : A1;
        const int akk = (c & 3) * 32;

        // ---- A: 128 rows x 32 fp32 -> hi/lo bf16 (1024 float4 loads) ----
        #pragma unroll
        for (int G = tid; G < 1024; G += 256) {
            int row = G >> 3, g = G & 7;
            int gr = rowBase + row;
            float4 u = make_float4(0.f, 0.f, 0.f, 0.f);
            if (gr < N_NODES)
                u = *(const float4*)(Asrc + (size_t)gr * lda + akk + g * 4);
            float v[4] = {u.x, u.y, u.z, u.w};
            int base = row * A_LD + g * 4;
            uint2 lo, hi = pack4_hi_lo(v, lo);
            *(uint2*)&sm.t.ah[base] = hi;
            *(uint2*)&sm.t.al[base] = lo;
        }
        // ---- B: 64 n x 32 k bf16 hi + lo (uint4 = 8 bf16 per load) ----
        {
            int n = tid >> 2, g = tid & 3;
            uint4 vh = *(const uint4*)(BT_hi + (size_t)(colBase + n) * 256 + kk + g * 8);
            uint4 vl = *(const uint4*)(BT_lo + (size_t)(colBase + n) * 256 + kk + g * 8);
            *(uint4*)&sm.t.bh[n * B_LD + g * 8] = vh;
            *(uint4*)&sm.t.bl[n * B_LD + g * 8] = vl;
        }
        __syncthreads();

        // ---- 2 k16 steps ----
        #pragma unroll
        for (int ks = 0; ks < 2; ++ks) {
            wmma::fragment<wmma::matrix_a, 16, 16, 16, __nv_bfloat16, wmma::row_major> aH[2], aL[2];
            wmma::fragment<wmma::matrix_b, 16, 16, 16, __nv_bfloat16, wmma::col_major> bH[2], bL[2];
            #pragma unroll
            for (int mt = 0; mt < 2; ++mt) {
                int r0 = warpM * 32 + mt * 16;
                wmma::load_matrix_sync(aH[mt], &sm.t.ah[r0 * A_LD + ks * 16], A_LD);
                wmma::load_matrix_sync(aL[mt], &sm.t.al[r0 * A_LD + ks * 16], A_LD);
            }
            #pragma unroll
            for (int nt = 0; nt < 2; ++nt) {
                int n0 = warpN * 32 + nt * 16;
                wmma::load_matrix_sync(bH[nt], &sm.t.bh[n0 * B_LD + ks * 16], B_LD);
                wmma::load_matrix_sync(bL[nt], &sm.t.bl[n0 * B_LD + ks * 16], B_LD);
            }
            #pragma unroll
            for (int mt = 0; mt < 2; ++mt)
                #pragma unroll
                for (int nt = 0; nt < 2; ++nt) {
                    wmma::mma_sync(acc[mt][nt], aH[mt], bH[nt], acc[mt][nt]);
                    wmma::mma_sync(acc[mt][nt], aH[mt], bL[nt], acc[mt][nt]);
                    wmma::mma_sync(acc[mt][nt], aL[mt], bH[nt], acc[mt][nt]);
                }
        }
        __syncthreads();
    }

    // ---- epilogue: stage in smem, then bias/relu on copy-out ----
    #pragma unroll
    for (int mt = 0; mt < 2; ++mt)
        #pragma unroll
        for (int nt = 0; nt < 2; ++nt) {
            int r0 = warpM * 32 + mt * 16;
            int c0 = warpN * 32 + nt * 16;
            wmma::store_matrix_sync(&sm.stage[r0 * 64 + c0], acc[mt][nt], 64,
                                    wmma::mem_row_major);
        }
    __syncthreads();

    #pragma unroll
    for (int G = tid; G < 2048; G += 256) {
        int row = G >> 4, g = G & 15;
        int gr = rowBase + row;
        if (gr >= N_NODES) continue;
        float4 v = *(const float4*)&sm.stage[row * 64 + g * 4];
        float w[4] = {v.x, v.y, v.z, v.w};
        if (mode == 1) {
            int col = colBase + g * 4;
            #pragma unroll
            for (int q = 0; q < 4; ++q) w[q] = fmaxf(w[q] + bias[col + q], 0.f);
            *(float4*)(g_h + (size_t)gr * NHID + col) = make_float4(w[0], w[1], w[2], w[3]);
        } else {
            int col = g * 4;  // local 0..63
            if (colBase == 0) {
                *(float4*)(g_p2 + (size_t)gr * NCLASS + col) = make_float4(w[0], w[1], w[2], w[3]);
            } else {
                #pragma unroll
                for (int q = 0; q < 4; ++q) w[q] += bias[col + q];
                *(float4*)(out2 + (size_t)gr * NCLASS + col) = make_float4(w[0], w[1], w[2], w[3]);
            }
        }
    }
}

// ===========================================================================
extern "C" void kernel_launch(void* const* d_in, const int* in_sizes, int n_in,
                              void* d_out, int out_size) {
    const float* x   = (const float*)d_in[0];
    const void*  ei  = d_in[1];
    const float* W1n = (const float*)d_in[2];
    const float* W1r = (const float*)d_in[3];
    const float* b1  = (const float*)d_in[4];
    const float* W2n = (const float*)d_in[5];
    const float* W2r = (const float*)d_in[6];
    const float* b2  = (const float*)d_in[7];
    float* out = (float*)d_out;

    // zero degrees + dtype detect (fused) ; weight prepack
    zero_deg_kernel<<<(N_NODES + 255) / 256, 256>>>((const int*)ei);
    prepack_kernel<<<(256 * 256 + 128 * 256 + 255) / 256, 256>>>(W1n, W1r, W2n, W2r);

    // CSR build
    hist_kernel<<<(N_EDGES + 255) / 256, 256>>>(ei);
    scan_part_kernel<<<NPART, 256>>>();
    scan_top_kernel<<<1, 256>>>();
    scan_fin_kernel<<<NPART, 256>>>();
    fill_kernel<<<(N_EDGES + 255) / 256, 256>>>(ei);

    // layer1 aggregation
    {
        long long threads = (long long)N_NODES * 32;
        agg_x_kernel<<<(int)((threads + 255) / 256), 256>>>(x);
    }
    // layer1 GEMM (wmma): h = relu([meanx|x] @ [W1n;W1r] + b1)
    {
        dim3 grid((N_NODES + 127) / 128, NHID / 64);
        wmma_gemm_kernel<<<grid, 256>>>(x, b1, nullptr, 1);
    }
    // layer2 fused GEMM: colBase 0 -> p2 = h@W2n ; colBase 64 -> out = h@W2r + b2
    {
        dim3 grid((N_NODES + 127) / 128, 2);
        wmma_gemm_kernel<<<grid, 256>>>(x, b2, out, 2);
    }
    // layer2 aggregation
    {
        long long threads = (long long)N_NODES * 32;
        agg_p_kernel<<<(int)((threads + 255) / 256), 256>>>(out);
    }
}